// round 17
// baseline (speedup 1.0000x reference)
#include <cuda_runtime.h>
#include <cuda_bf16.h>
#include <cstdint>

#define N_ITEMS  262144
#define DIM      128
#define NCB      3
#define KCW      256
#define TM       16               // items per pair-tile
#define NTILES   (N_ITEMS / TM)   // 16384
#define NTHREADS 256
#define GRID     296
#define NPAIR    (GRID * 4)       // 1184
#define RSW      132
#define MCOEF    0.040f

__device__ float g_cc[NCB * KCW];
__device__ int   g_cmax[NCB];
__device__ uint4 g_bfrag[NCB * 2 * 8 * 8 * 32];   // [stage][half][ntp][ks][lane]

__device__ __forceinline__ uint32_t s2u(const void* p) {
    return (uint32_t)__cvta_generic_to_shared(p);
}
#define CPA16(saddr, gptr) asm volatile("cp.async.ca.shared.global [%0], [%1], 16;" :: "r"(saddr), "l"(gptr))
#define CPCOMMIT()         asm volatile("cp.async.commit_group;")
#define CPWAIT0()          asm volatile("cp.async.wait_group 0;" ::: "memory")
#define CPWAIT1()          asm volatile("cp.async.wait_group 1;" ::: "memory")
#define PBAR(id)           asm volatile("bar.sync %0, 64;" :: "r"(id) : "memory")
#define MMA16816(d,a0,a1,a2,a3,b0,b1) asm volatile( \
    "mma.sync.aligned.m16n8k16.row.col.f32.bf16.bf16.f32 " \
    "{%0,%1,%2,%3}, {%4,%5,%6,%7}, {%8,%9}, {%0,%1,%2,%3};" \
    : "+f"((d)[0]),"+f"((d)[1]),"+f"((d)[2]),"+f"((d)[3]) \
    : "r"(a0),"r"(a1),"r"(a2),"r"(a3),"r"(b0),"r"(b1))
#define CVTBF2(o, lo, hi) asm("cvt.rn.bf16x2.f32 %0, %1, %2;" : "=r"(o) : "f"(hi), "f"(lo))

__device__ __forceinline__ uint32_t ford(float f) {
    uint32_t u = __float_as_uint(f);
    return (u & 0x80000000u) ? ~u : (u | 0x80000000u);
}

// ---- ||c||^2: 8 threads/row, double partials + shfl (double slack >> fp32 grid) ----
__global__ void cc_kernel(const float* __restrict__ codebooks) {
    int idx = blockIdx.x * 256 + threadIdx.x;     // 0..6143
    if (idx >= NCB * KCW * 8) return;
    int row = idx >> 3, part = idx & 7;
    const float* r = codebooks + (size_t)row * DIM + part * 16;
    double s = 0.0;
    #pragma unroll
    for (int k = 0; k < 16; k++) { double v = (double)r[k]; s += v * v; }
    s += __shfl_xor_sync(0xffffffffu, s, 1);
    s += __shfl_xor_sync(0xffffffffu, s, 2);
    s += __shfl_xor_sync(0xffffffffu, s, 4);
    if (part == 0) {
        g_cc[row] = (float)s;
        float nrm = sqrtf((float)s) * 1.0001f;
        atomicMax(&g_cmax[row / KCW], __float_as_int(nrm));
    }
}

__global__ void bfrag_kernel(const float* __restrict__ codebooks) {
    int idx = blockIdx.x * 256 + threadIdx.x;     // 0..12287
    if (idx >= NCB * 2 * 8 * 8 * 32) return;
    int lane = idx & 31, ks = (idx >> 5) & 7, ntp = (idx >> 8) & 7;
    int cb = (idx >> 11) & 1, stage = idx >> 12;
    int n0 = cb * 128 + ntp * 16 + (lane >> 2);
    int kb = ks * 16 + (lane & 3) * 2;
    const float* B = codebooks + (size_t)stage * KCW * DIM;
    auto pk = [&](int row, int col) {
        uint32_t lo = (uint32_t)__bfloat16_as_ushort(__float2bfloat16(B[(size_t)row * DIM + col]));
        uint32_t hi = (uint32_t)__bfloat16_as_ushort(__float2bfloat16(B[(size_t)row * DIM + col + 1]));
        return lo | (hi << 16);
    };
    uint4 o;
    o.x = pk(n0,     kb);
    o.y = pk(n0,     kb + 8);
    o.z = pk(n0 + 8, kb);
    o.w = pk(n0 + 8, kb + 8);
    g_bfrag[idx] = o;
}

// exact d2: sequential k-ascending fmaf chain (validated R3-R16)
__device__ __noinline__ float exact_d2(const float* __restrict__ r,
                                       const float* __restrict__ c,
                                       float rr, float ccj) {
    float dot = 0.f;
    #pragma unroll
    for (int m = 0; m < 32; m++) {
        float4 a = ((const float4*)r)[m];
        float4 b = ((const float4*)c)[m];
        dot = __fmaf_rn(a.x, b.x, dot);
        dot = __fmaf_rn(a.y, b.y, dot);
        dot = __fmaf_rn(a.z, b.z, dot);
        dot = __fmaf_rn(a.w, b.w, dot);
    }
    return __fadd_rn(__fmaf_rn(-2.f, dot, rr), ccj);
}

// per-pair smem block (bytes within pair block)
#define PO_R0    0        // 8448
#define PO_R1    8448     // 8448
#define PO_RRS   16896    // 64
#define PO_HM    16960    // 128
#define PO_EKEY  17088    // 2*16*8 = 256 (ping-pong by stage parity)
#define PO_BEST  17344    // 128 (stages 0,1)
#define PP       17536
#define O_CC     (4 * PP) // 70144; cc 3072
#define SMEM_BYTES (O_CC + 3072 + 1024)

__global__ __launch_bounds__(NTHREADS, 2)
void rvq_kernel(const float* __restrict__ x,
                const float* __restrict__ codebooks,
                float* __restrict__ out, int mode)
{
    extern __shared__ char smraw[];
    char* smem = (char*)(((uintptr_t)smraw + 1023) & ~(uintptr_t)1023);
    float* cc_s = (float*)(smem + O_CC);      // [3][256]

    const int t = threadIdx.x;
    const int pair = t >> 6;
    const int tp   = t & 63;
    const int wp   = (t >> 5) & 1;
    const int lane = t & 31;
    const int barid = pair + 1;

    char* pb = smem + pair * PP;
    float* rawb[2] = { (float*)(pb + PO_R0), (float*)(pb + PO_R1) };
    float* rrs  = (float*)(pb + PO_RRS);
    float* hm   = (float*)(pb + PO_HM);       // [2][16]
    unsigned long long* ekey = (unsigned long long*)(pb + PO_EKEY);   // [2][16]
    int*   best = (int*)(pb + PO_BEST);       // [2][16]

    cc_s[t] = g_cc[t];
    cc_s[256 + t] = g_cc[256 + t];
    cc_s[512 + t] = g_cc[512 + t];
    float cmax3[3];
    #pragma unroll
    for (int s = 0; s < 3; s++) cmax3[s] = __int_as_float(g_cmax[s]);
    __syncthreads();

    const int colbase = 128 * wp;

    auto prefetch_tile = [&](int tl, int buf) {
        const char* gb = (const char*)(x + (size_t)tl * (TM * DIM));
        uint32_t sb = s2u(rawb[buf]);
        #pragma unroll
        for (int n = 0; n < 8; n++) {
            int g = tp + 64 * n;
            CPA16(sb + (g >> 5) * (RSW * 4) + (g & 31) * 16, gb + g * 16);
        }
        CPCOMMIT();
    };

    const int P = blockIdx.x * 4 + pair;
    int tl0 = P;
    if (tl0 < NTILES) prefetch_tile(tl0, 0);

    int it = 0;
    for (int tl = tl0; tl < NTILES; tl += NPAIR, it++) {
        int buf = it & 1;
        float* raw = rawb[buf];

        int tln = tl + NPAIR;
        if (tln < NTILES) { prefetch_tile(tln, buf ^ 1); CPWAIT1(); }
        else              { CPWAIT0(); }
        PBAR(barid);                          // raw ready pair-wide; prev tile done

        // ---- rr (validated chains) + ekey[0] init ----
        {
            int i = tp >> 2, q = tp & 3;
            const float4* rp = (const float4*)(raw + i * RSW + q * 32);
            double s = 0.0;
            #pragma unroll
            for (int m = 0; m < 8; m++) {
                float4 v = rp[m];
                double a = v.x, b = v.y, c = v.z, d = v.w;
                s += a * a; s += b * b; s += c * c; s += d * d;
            }
            s += __shfl_xor_sync(0xffffffffu, s, 1);
            s += __shfl_xor_sync(0xffffffffu, s, 2);
            if (q == 0) rrs[i] = (float)s;
            if (tp < TM) ekey[tp] = ~0ull;    // buffer 0 (stage 0)
        }
        PBAR(barid);

        for (int stage = 0; stage < NCB; stage++) {
            const float* ccst = cc_s + stage * KCW;
            const float cmax = cmax3[stage];
            unsigned long long* ek = ekey + (stage & 1) * TM;

            // ---- MMA: 16 items x 128 cw; B frags from L2 ----
            float d[16][4];
            #pragma unroll
            for (int nt = 0; nt < 16; nt++)
                #pragma unroll
                for (int e = 0; e < 4; e++) d[nt][e] = 0.f;

            const float* ar0 = raw + (lane >> 2) * RSW + (lane & 3) * 2;
            const float* ar1 = ar0 + 8 * RSW;
            const uint4* bf = g_bfrag + (size_t)(stage * 2 + wp) * 2048 + lane;

            #pragma unroll 1
            for (int ks = 0; ks < 8; ks++) {
                uint4 bv[8];
                #pragma unroll
                for (int ntp = 0; ntp < 8; ntp++)
                    bv[ntp] = __ldg(bf + (ntp * 8 + ks) * 32);
                int k0 = ks * 16;
                float2 f0 = *(const float2*)(ar0 + k0);
                float2 f1 = *(const float2*)(ar1 + k0);
                float2 f2 = *(const float2*)(ar0 + k0 + 8);
                float2 f3 = *(const float2*)(ar1 + k0 + 8);
                uint32_t a0, a1, a2, a3;
                CVTBF2(a0, f0.x, f0.y);
                CVTBF2(a1, f1.x, f1.y);
                CVTBF2(a2, f2.x, f2.y);
                CVTBF2(a3, f3.x, f3.y);
                #pragma unroll
                for (int ntp = 0; ntp < 8; ntp++) {
                    MMA16816(d[2 * ntp],     a0, a1, a2, a3, bv[ntp].x, bv[ntp].y);
                    MMA16816(d[2 * ntp + 1], a0, a1, a2, a3, bv[ntp].z, bv[ntp].w);
                }
            }

            // ---- approx d2 + per-half min ----
            const int item0 = lane >> 2;
            const int item1 = item0 + 8;
            const float rr0 = rrs[item0], rr1 = rrs[item1];
            float mn0 = 3.0e38f, mn1 = 3.0e38f;
            #pragma unroll
            for (int nt = 0; nt < 16; nt++) {
                int n = colbase + nt * 8 + 2 * (lane & 3);
                float c0 = ccst[n], c1 = ccst[n + 1];
                d[nt][0] = __fadd_rn(__fmaf_rn(-2.f, d[nt][0], rr0), c0);
                d[nt][1] = __fadd_rn(__fmaf_rn(-2.f, d[nt][1], rr0), c1);
                d[nt][2] = __fadd_rn(__fmaf_rn(-2.f, d[nt][2], rr1), c0);
                d[nt][3] = __fadd_rn(__fmaf_rn(-2.f, d[nt][3], rr1), c1);
                mn0 = fminf(mn0, fminf(d[nt][0], d[nt][1]));
                mn1 = fminf(mn1, fminf(d[nt][2], d[nt][3]));
            }
            mn0 = fminf(mn0, __shfl_xor_sync(0xffffffffu, mn0, 1));
            mn0 = fminf(mn0, __shfl_xor_sync(0xffffffffu, mn0, 2));
            mn1 = fminf(mn1, __shfl_xor_sync(0xffffffffu, mn1, 1));
            mn1 = fminf(mn1, __shfl_xor_sync(0xffffffffu, mn1, 2));
            if ((lane & 3) == 0) {
                hm[wp * TM + item0] = mn0;
                hm[wp * TM + item1] = mn1;
            }
            PBAR(barid);                      // hm exchange

            // ---- inline rescue: each lane exact-evaluates its own candidates ----
            {
                float thr0 = fminf(hm[item0], hm[TM + item0]) + MCOEF * sqrtf(rr0) * cmax + 1e-3f;
                float thr1 = fminf(hm[item1], hm[TM + item1]) + MCOEF * sqrtf(rr1) * cmax + 1e-3f;
                const float* cb0 = codebooks + (size_t)stage * KCW * DIM;
                #pragma unroll
                for (int nt = 0; nt < 16; nt++) {
                    int n = colbase + nt * 8 + 2 * (lane & 3);
                    #pragma unroll
                    for (int e = 0; e < 4; e++) {
                        int iti = (e < 2) ? item0 : item1;
                        float thr = (e < 2) ? thr0 : thr1;
                        float rrv = (e < 2) ? rr0 : rr1;
                        if (d[nt][e] <= thr) {
                            int j = n + (e & 1);
                            float ex = exact_d2(raw + iti * RSW, cb0 + (size_t)j * DIM,
                                                rrv, ccst[j]);
                            unsigned long long key =
                                ((unsigned long long)ford(ex) << 32) | (uint32_t)j;
                            atomicMin(&ek[iti], key);
                        }
                    }
                }
            }
            PBAR(barid);                      // ekey complete pair-wide

            // ---- decide + update / quantize ----
            {
                int i = tp >> 2, q = tp & 3, off = q * 32;
                int bi = (int)(ek[i] & 0xffffffffu);
                int gi = tl * TM + i;
                if (q == 0) {
                    if (stage < 2) best[stage * TM + i] = bi;
                    if (mode == 0)      out[(size_t)gi * 3 + stage] = (float)bi;
                    else if (mode == 2) ((int*)out)[(size_t)gi * 3 + stage] = bi;
                }
                if (stage < 2) {
                    const float4* cr = (const float4*)(codebooks + ((size_t)stage * KCW + bi) * DIM + off);
                    float4* rg = (float4*)(raw + i * RSW + off);
                    double s = 0.0;
                    #pragma unroll
                    for (int m = 0; m < 8; m++) {
                        float4 r = rg[m], c = cr[m], o;
                        o.x = __fsub_rn(r.x, c.x); o.y = __fsub_rn(r.y, c.y);
                        o.z = __fsub_rn(r.z, c.z); o.w = __fsub_rn(r.w, c.w);
                        rg[m] = o;
                        double a = o.x, b2 = o.y, c2 = o.z, d2 = o.w;
                        s += a * a; s += b2 * b2; s += c2 * c2; s += d2 * d2;
                    }
                    s += __shfl_xor_sync(0xffffffffu, s, 1);
                    s += __shfl_xor_sync(0xffffffffu, s, 2);
                    if (q == 0) rrs[i] = (float)s;
                    if (tp < TM) ekey[((stage + 1) & 1) * TM + tp] = ~0ull;  // init next buffer
                    PBAR(barid);              // residual + rrs + next ekey ready
                } else if (mode != 2) {
                    int i0 = best[0 * TM + i], i1 = best[1 * TM + i];
                    const float4* c0 = (const float4*)(codebooks + (size_t)i0 * DIM + off);
                    const float4* c1 = (const float4*)(codebooks + ((size_t)KCW + i1) * DIM + off);
                    const float4* c2 = (const float4*)(codebooks + ((size_t)2 * KCW + bi) * DIM + off);
                    float* outq = (mode == 0) ? (out + (size_t)N_ITEMS * 3) : out;
                    float4* go = (float4*)(outq + (size_t)gi * DIM + off);
                    #pragma unroll
                    for (int m = 0; m < 8; m++) {
                        float4 a = c0[m], b = c1[m], c = c2[m], o;
                        o.x = __fadd_rn(__fadd_rn(a.x, b.x), c.x);
                        o.y = __fadd_rn(__fadd_rn(a.y, b.y), c.y);
                        o.z = __fadd_rn(__fadd_rn(a.z, b.z), c.z);
                        o.w = __fadd_rn(__fadd_rn(a.w, b.w), c.w);
                        go[m] = o;
                    }
                }
            }
        }
    }
}

extern "C" void kernel_launch(void* const* d_in, const int* in_sizes, int n_in,
                              void* d_out, int out_size)
{
    const float* x   = (const float*)d_in[0];
    const float* cbk = (const float*)d_in[1];
    if (n_in >= 2 && in_sizes[0] == NCB * KCW * DIM && in_sizes[1] == N_ITEMS * DIM) {
        const float* tmp = x; x = cbk; cbk = tmp;
    }
    int mode;
    if (out_size == N_ITEMS * (3 + DIM))      mode = 0;
    else if (out_size == N_ITEMS * DIM)       mode = 1;
    else if (out_size == N_ITEMS * 3)         mode = 2;
    else                                       mode = (out_size > N_ITEMS * DIM) ? 0 : 1;

    cc_kernel<<<24, 256>>>(cbk);
    bfrag_kernel<<<48, 256>>>(cbk);
    cudaFuncSetAttribute(rvq_kernel, cudaFuncAttributeMaxDynamicSharedMemorySize, SMEM_BYTES);
    rvq_kernel<<<GRID, NTHREADS, SMEM_BYTES>>>(x, cbk, (float*)d_out, mode);
}